// round 3
// baseline (speedup 1.0000x reference)
#include <cuda_runtime.h>

// NeighborlistForInference: brute-force N^2 upper-triangular pair list.
//
// Inputs (metadata order):
//   d_in[0] : positions   [n*3]  float32
//   d_in[1] : box_vectors [9]    float32 (diag = box lengths)
//   d_in[2] : is_periodic [1]    int32
//
// Output layout (flattened reference tuple, fp32, total 6*P elements):
//   [0      , P)   : i index per pair (or -1 if out of cutoff)
//   [P      , 2P)  : j index per pair (or -1)
//   [2P     , 3P)  : d_ij (or 0)
//   [3P     , 6P)  : r_ij row-major [P,3] (or 0)
//
// Mapping: blockIdx.y = i, (blockIdx.x,threadIdx.x) = j. Consecutive lanes
// write consecutive pair slots p = i*(2n-i-1)/2 + (j-i-1) -> all six store
// streams fully coalesced. Kernel is store-bandwidth bound (~432 MB out).

#ifndef NL_CUTOFF
#define NL_CUTOFF 0.5f
#endif

__global__ __launch_bounds__(256)
void neighborlist_kernel(const float* __restrict__ pos,
                         const float* __restrict__ box,
                         const int*   __restrict__ is_periodic,
                         float*       __restrict__ out,
                         int n, long long P)
{
    const int i = blockIdx.y;
    const int j = blockIdx.x * blockDim.x + threadIdx.x;
    if (j <= i || j >= n) return;

    // Warp-uniform broadcast loads (L1-resident after first touch).
    const float Lx = box[0];
    const float Ly = box[4];
    const float Lz = box[8];
    const int   per = *is_periodic;

    const float xi = pos[3 * i + 0];
    const float yi = pos[3 * i + 1];
    const float zi = pos[3 * i + 2];

    const float xj = pos[3 * j + 0];
    const float yj = pos[3 * j + 1];
    const float zj = pos[3 * j + 2];

    float rx = xi - xj;
    float ry = yi - yj;
    float rz = zi - zj;

    if (per) {
        // jnp.remainder(r + L/2, L) - L/2  (numpy-mod: result sign follows divisor)
        const float hx = 0.5f * Lx, hy = 0.5f * Ly, hz = 0.5f * Lz;
        float tx = fmodf(rx + hx, Lx); if (tx < 0.0f) tx += Lx; rx = tx - hx;
        float ty = fmodf(ry + hy, Ly); if (ty < 0.0f) ty += Ly; ry = ty - hy;
        float tz = fmodf(rz + hz, Lz); if (tz < 0.0f) tz += Lz; rz = tz - hz;
    }

    const float d = sqrtf(rx * rx + ry * ry + rz * rz);
    const bool  in = (d <= NL_CUTOFF);

    // Linear pair index in triu(i<j) order. Fits int64 comfortably.
    const long long start_i = (long long)i * (2LL * n - i - 1LL) / 2LL;
    const long long p       = start_i + (long long)(j - i - 1);

    const float fi = in ? (float)i : -1.0f;
    const float fj = in ? (float)j : -1.0f;
    const float fd = in ? d        :  0.0f;
    const float ox = in ? rx : 0.0f;
    const float oy = in ? ry : 0.0f;
    const float oz = in ? rz : 0.0f;

    // Streaming stores: output is 3.4x L2, don't pollute it.
    __stcs(out + p,          fi);
    __stcs(out + P + p,      fj);
    __stcs(out + 2 * P + p,  fd);
    float* rbase = out + 3 * P + 3 * p;
    __stcs(rbase + 0, ox);
    __stcs(rbase + 1, oy);
    __stcs(rbase + 2, oz);
}

extern "C" void kernel_launch(void* const* d_in, const int* in_sizes, int n_in,
                              void* d_out, int out_size)
{
    const float* pos   = (const float*)d_in[0];
    const float* box   = (const float*)d_in[1];
    const int*   isper = (const int*)d_in[2];
    float*       out   = (float*)d_out;

    const int n = in_sizes[0] / 3;
    const long long P = (long long)n * (n - 1) / 2;

    dim3 block(256, 1, 1);
    dim3 grid((unsigned)((n + 255) / 256), (unsigned)n, 1);
    neighborlist_kernel<<<grid, block>>>(pos, box, isper, out, n, P);
}

// round 4
// speedup vs baseline: 1.1739x; 1.1739x over previous
#include <cuda_runtime.h>

// NeighborlistForInference: brute-force N^2 upper-triangular pair list.
//
// Output layout (fp32, 6*P elements, P = n(n-1)/2):
//   [0   ,  P) : i index per pair (-1 if out of cutoff)
//   [P   , 2P) : j index per pair (-1)
//   [2P  , 3P) : d_ij (0)
//   [3P  , 6P) : r_ij row-major [P,3] (0)
//
// Round-3 redesign: flatten over pair index. Each thread owns 4 consecutive
// pairs p0=4t, inverts the triangular index once (float sqrt + integer fixup,
// exact), and emits 6 x STG.128 instead of 24 x STG.32. All offsets 32-bit.

#ifndef NL_CUTOFF
#define NL_CUTOFF 0.5f
#endif

__device__ __forceinline__ int tri_start(int i, int n) {
    // first pair index of row i:  i*(2n-i-1)/2   (max ~36M, fits int32)
    return (i * (2 * n - i - 1)) >> 1;
}

__device__ __forceinline__ float pbc_wrap(float r, float L, float h) {
    // jnp.remainder(r + L/2, L) - L/2  (numpy-mod: sign follows divisor)
    float t = fmodf(r + h, L);
    if (t < 0.0f) t += L;
    return t - h;
}

__global__ __launch_bounds__(256)
void neighborlist_kernel(const float* __restrict__ pos,
                         const float* __restrict__ box,
                         const int*   __restrict__ is_periodic,
                         float*       __restrict__ out,
                         int n, int P)
{
    const int numVec = P >> 2;             // full 4-pair groups
    const int t = blockIdx.x * blockDim.x + threadIdx.x;
    if (t > numVec) return;
    const int cnt = (t < numVec) ? 4 : (P & 3);
    if (cnt == 0) return;

    const int p0 = t << 2;

    // ---- invert triangular index: find row i with start(i) <= p0 < start(i+1)
    const int a = 2 * n - 1;
    const int disc = a * a - 8 * p0;       // = (a-2i)^2 at row starts; >= 1
    int i = (int)(0.5f * ((float)a - sqrtf((float)disc)));
    if (i < 0) i = 0;
    if (i > n - 2) i = n - 2;
    while (p0 < tri_start(i, n)) --i;                          // fixup (<=2 iters)
    while (i < n - 2 && p0 >= tri_start(i + 1, n)) ++i;
    int j = i + 1 + (p0 - tri_start(i, n));

    // ---- uniform params
    const float Lx = box[0], Ly = box[4], Lz = box[8];
    const float hx = 0.5f * Lx, hy = 0.5f * Ly, hz = 0.5f * Lz;
    const int per = *is_periodic;

    float xi = pos[3 * i + 0], yi = pos[3 * i + 1], zi = pos[3 * i + 2];

    float fi[4], fj[4], fd[4], rx[4], ry[4], rz[4];

    #pragma unroll
    for (int k = 0; k < 4; ++k) {
        if (k >= cnt) { fi[k] = fj[k] = fd[k] = rx[k] = ry[k] = rz[k] = 0.0f; continue; }
        if (j >= n) {                       // crossed to next row
            ++i; j = i + 1;
            xi = pos[3 * i + 0]; yi = pos[3 * i + 1]; zi = pos[3 * i + 2];
        }
        float dx = xi - pos[3 * j + 0];
        float dy = yi - pos[3 * j + 1];
        float dz = zi - pos[3 * j + 2];
        if (per) {
            dx = pbc_wrap(dx, Lx, hx);
            dy = pbc_wrap(dy, Ly, hy);
            dz = pbc_wrap(dz, Lz, hz);
        }
        const float d  = sqrtf(dx * dx + dy * dy + dz * dz);
        const bool  in = (d <= NL_CUTOFF);
        fi[k] = in ? (float)i : -1.0f;
        fj[k] = in ? (float)j : -1.0f;
        fd[k] = in ? d        :  0.0f;
        rx[k] = in ? dx : 0.0f;
        ry[k] = in ? dy : 0.0f;
        rz[k] = in ? dz : 0.0f;
        ++j;
    }

    if (cnt == 4) {
        // p0 % 4 == 0 and P % 4 == 0  ->  every stream address is 16B-aligned
        __stcs((float4*)(out + p0),           make_float4(fi[0], fi[1], fi[2], fi[3]));
        __stcs((float4*)(out + P + p0),       make_float4(fj[0], fj[1], fj[2], fj[3]));
        __stcs((float4*)(out + 2 * P + p0),   make_float4(fd[0], fd[1], fd[2], fd[3]));
        float* rb = out + 3 * P + 3 * p0;     // 3*p0 = 12t, 16B-aligned
        __stcs((float4*)(rb + 0), make_float4(rx[0], ry[0], rz[0], rx[1]));
        __stcs((float4*)(rb + 4), make_float4(ry[1], rz[1], rx[2], ry[2]));
        __stcs((float4*)(rb + 8), make_float4(rz[2], rx[3], ry[3], rz[3]));
    } else {
        // scalar tail (only if P % 4 != 0; not hit for n=6000)
        for (int k = 0; k < cnt; ++k) {
            const int p = p0 + k;
            __stcs(out + p,         fi[k]);
            __stcs(out + P + p,     fj[k]);
            __stcs(out + 2 * P + p, fd[k]);
            float* rb = out + 3 * P + 3 * p;
            __stcs(rb + 0, rx[k]);
            __stcs(rb + 1, ry[k]);
            __stcs(rb + 2, rz[k]);
        }
    }
}

extern "C" void kernel_launch(void* const* d_in, const int* in_sizes, int n_in,
                              void* d_out, int out_size)
{
    const float* pos   = (const float*)d_in[0];
    const float* box   = (const float*)d_in[1];
    const int*   isper = (const int*)d_in[2];
    float*       out   = (float*)d_out;

    const int n = in_sizes[0] / 3;
    const int P = (int)((long long)n * (n - 1) / 2);   // 17,997,000 for n=6000

    const int numThreads = (P >> 2) + 1;               // vector threads + tail
    const int block = 256;
    const int grid  = (numThreads + block - 1) / block;
    neighborlist_kernel<<<grid, block>>>(pos, box, isper, out, n, P);
}

// round 5
// speedup vs baseline: 1.3589x; 1.1577x over previous
#include <cuda_runtime.h>

// NeighborlistForInference: brute-force N^2 upper-triangular pair list.
//
// Output layout (fp32, 6*P elements, P = n(n-1)/2):
//   [0   ,  P) : i index per pair (-1 if out of cutoff)
//   [P   , 2P) : j index per pair (-1)
//   [2P  , 3P) : d_ij (0)
//   [3P  , 6P) : r_ij row-major [P,3] (0)
//
// Round-4: kill instruction overhead.
//  * fmodf-based PBC replaced by single conditional +/-L wrap. Bitwise
//    identical for r in (-L, L): Sterbenz makes t-L exact on [L, 1.5L),
//    and the t<0 branch performs the same t+L fp op the remainder path does.
//  * (float)i row-constant, (float)j running +1.0f (exact below 2^24).
//  * six output base pointers passed as args -> 1 IMAD.WIDE per stream.
//  * mask + value both from IEEE sqrtf (exact reference semantics).

#ifndef NL_CUTOFF
#define NL_CUTOFF 0.5f
#endif

__device__ __forceinline__ int tri_start(int i, int n) {
    return (i * (2 * n - i - 1)) >> 1;     // row start, max ~36M fits int32
}

__global__ __launch_bounds__(256)
void neighborlist_kernel(const float* __restrict__ pos,
                         const float* __restrict__ box,
                         const int*   __restrict__ is_periodic,
                         float* __restrict__ out_i,
                         float* __restrict__ out_j,
                         float* __restrict__ out_d,
                         float* __restrict__ out_r,
                         int n, int P)
{
    const int numVec = P >> 2;
    const int t = blockIdx.x * blockDim.x + threadIdx.x;
    if (t > numVec) return;
    const int cnt = (t < numVec) ? 4 : (P & 3);
    if (cnt == 0) return;

    const int p0 = t << 2;

    // ---- invert triangular index (float sqrt estimate + exact fixup)
    const int a = 2 * n - 1;
    const int disc = a * a - 8 * p0;
    int i = (int)(0.5f * ((float)a - sqrtf((float)disc)));
    if (i < 0) i = 0;
    if (i > n - 2) i = n - 2;
    while (p0 < tri_start(i, n)) --i;
    while (i < n - 2 && p0 >= tri_start(i + 1, n)) ++i;
    int j = i + 1 + (p0 - tri_start(i, n));

    const float Lx = box[0], Ly = box[4], Lz = box[8];
    const float hx = 0.5f * Lx, hy = 0.5f * Ly, hz = 0.5f * Lz;
    const int per = *is_periodic;

    float xi = pos[3 * i + 0], yi = pos[3 * i + 1], zi = pos[3 * i + 2];
    float fi_f = (float)i;
    float fj_f = (float)j;

    float fi[4], fj[4], fd[4], rx[4], ry[4], rz[4];

    #pragma unroll
    for (int k = 0; k < 4; ++k) {
        if (k >= cnt) { fi[k] = fj[k] = fd[k] = rx[k] = ry[k] = rz[k] = 0.0f; continue; }
        if (j >= n) {                       // rare row crossing
            ++i; j = i + 1;
            xi = pos[3 * i + 0]; yi = pos[3 * i + 1]; zi = pos[3 * i + 2];
            fi_f = (float)i; fj_f = (float)j;
        }
        float dx = xi - pos[3 * j + 0];
        float dy = yi - pos[3 * j + 1];
        float dz = zi - pos[3 * j + 2];
        if (per) {
            // exact minimum-image for r in (-L, L): t in (-L/2, 3L/2)
            float tx = dx + hx; tx = (tx >= Lx) ? tx - Lx : tx; tx = (tx < 0.0f) ? tx + Lx : tx; dx = tx - hx;
            float ty = dy + hy; ty = (ty >= Ly) ? ty - Ly : ty; ty = (ty < 0.0f) ? ty + Ly : ty; dy = ty - hy;
            float tz = dz + hz; tz = (tz >= Lz) ? tz - Lz : tz; tz = (tz < 0.0f) ? tz + Lz : tz; dz = tz - hz;
        }
        const float d  = sqrtf(dx * dx + dy * dy + dz * dz);   // IEEE
        const bool  in = (d <= NL_CUTOFF);
        fi[k] = in ? fi_f : -1.0f;
        fj[k] = in ? fj_f : -1.0f;
        fd[k] = in ? d    :  0.0f;
        rx[k] = in ? dx : 0.0f;
        ry[k] = in ? dy : 0.0f;
        rz[k] = in ? dz : 0.0f;
        ++j; fj_f += 1.0f;                  // exact: j < 2^24
    }

    if (cnt == 4) {
        // P % 4 == 0 -> all six stream addresses 16B-aligned
        __stcs((float4*)(out_i + p0), make_float4(fi[0], fi[1], fi[2], fi[3]));
        __stcs((float4*)(out_j + p0), make_float4(fj[0], fj[1], fj[2], fj[3]));
        __stcs((float4*)(out_d + p0), make_float4(fd[0], fd[1], fd[2], fd[3]));
        float* rb = out_r + 3 * p0;         // 12t floats, 16B-aligned
        __stcs((float4*)(rb + 0), make_float4(rx[0], ry[0], rz[0], rx[1]));
        __stcs((float4*)(rb + 4), make_float4(ry[1], rz[1], rx[2], ry[2]));
        __stcs((float4*)(rb + 8), make_float4(rz[2], rx[3], ry[3], rz[3]));
    } else {
        for (int k = 0; k < cnt; ++k) {
            const int p = p0 + k;
            __stcs(out_i + p, fi[k]);
            __stcs(out_j + p, fj[k]);
            __stcs(out_d + p, fd[k]);
            float* rb = out_r + 3 * p;
            __stcs(rb + 0, rx[k]);
            __stcs(rb + 1, ry[k]);
            __stcs(rb + 2, rz[k]);
        }
    }
}

extern "C" void kernel_launch(void* const* d_in, const int* in_sizes, int n_in,
                              void* d_out, int out_size)
{
    const float* pos   = (const float*)d_in[0];
    const float* box   = (const float*)d_in[1];
    const int*   isper = (const int*)d_in[2];
    float*       out   = (float*)d_out;

    const int n = in_sizes[0] / 3;
    const int P = (int)((long long)n * (n - 1) / 2);   // 17,997,000 for n=6000

    const int numThreads = (P >> 2) + 1;
    const int block = 256;
    const int grid  = (numThreads + block - 1) / block;
    neighborlist_kernel<<<grid, block>>>(pos, box, isper,
                                         out, out + P, out + 2 * (long long)P,
                                         out + 3 * (long long)P, n, P);
}